// round 13
// baseline (speedup 1.0000x reference)
#include <cuda_runtime.h>
#include <cuda_bf16.h>

#define T_STEPS 1000
#define BETA_1 1e-4
#define BETA_T 0.02

// ---- compile-time table: (sqrt(alpha_bar[t]), sqrt(1-alpha_bar[t])) ----

struct ScaleTable {
    float2 v[T_STEPS];
};

constexpr double csqrt(double x) {
    double g = x > 1.0 ? x : 1.0;
    for (int i = 0; i < 60; ++i) g = 0.5 * (g + x / g);
    return g;
}

constexpr ScaleTable make_table() {
    ScaleTable tbl{};
    const double slope = (BETA_T - BETA_1) / (double)(T_STEPS - 1);
    double ab = 1.0;
    for (int i = 0; i < T_STEPS; ++i) {
        double beta = BETA_1 + slope * (double)i;
        ab *= (1.0 - beta);
        tbl.v[i].x = (float)csqrt(ab);
        tbl.v[i].y = (float)csqrt(1.0 - ab);
    }
    return tbl;
}

__constant__ ScaleTable g_scales = make_table();

// ---- persistent grid-stride mix kernel ----
// Single wave: 608 CTAs (152 SMs x 4) x 512 threads; each thread strides
// through ~41 float4s. Eliminates all wave-transition / CTA launch overhead.
// 2-way unroll front-batches 4 independent LDG.128 per iteration pair.

#define BLK 512
#define GRID 608   // 152 SMs * 4 CTAs/SM = exactly one wave on GB300

__global__ void __launch_bounds__(BLK, 4) ddpm_mix_kernel(
    const float4* __restrict__ images,
    const float4* __restrict__ e,
    const int* __restrict__ t,
    float4* __restrict__ out,
    int total4)
{
    const int stride = GRID * BLK;
    int idx = blockIdx.x * BLK + threadIdx.x;

    // Main 2-way unrolled loop: iterations independent, loads front-batched.
    for (; idx + stride < total4; idx += 2 * stride) {
        const int j = idx + stride;
        float4 im0 = __ldcs(&images[idx]);
        float4 ee0 = __ldcs(&e[idx]);
        float4 im1 = __ldcs(&images[j]);
        float4 ee1 = __ldcs(&e[j]);

        const float2 sc0 = g_scales.v[__ldg(&t[(unsigned)idx / 196u])];
        float4 o0;
        o0.x = fmaf(sc0.x, im0.x, sc0.y * ee0.x);
        o0.y = fmaf(sc0.x, im0.y, sc0.y * ee0.y);
        o0.z = fmaf(sc0.x, im0.z, sc0.y * ee0.z);
        o0.w = fmaf(sc0.x, im0.w, sc0.y * ee0.w);
        __stcs(&out[idx], o0);

        const float2 sc1 = g_scales.v[__ldg(&t[(unsigned)j / 196u])];
        float4 o1;
        o1.x = fmaf(sc1.x, im1.x, sc1.y * ee1.x);
        o1.y = fmaf(sc1.x, im1.y, sc1.y * ee1.y);
        o1.z = fmaf(sc1.x, im1.z, sc1.y * ee1.z);
        o1.w = fmaf(sc1.x, im1.w, sc1.y * ee1.w);
        __stcs(&out[j], o1);
    }

    // Tail (at most one element per thread)
    if (idx < total4) {
        float4 im = __ldcs(&images[idx]);
        float4 ee = __ldcs(&e[idx]);
        const float2 sc = g_scales.v[__ldg(&t[(unsigned)idx / 196u])];
        float4 o;
        o.x = fmaf(sc.x, im.x, sc.y * ee.x);
        o.y = fmaf(sc.x, im.y, sc.y * ee.y);
        o.z = fmaf(sc.x, im.z, sc.y * ee.z);
        o.w = fmaf(sc.x, im.w, sc.y * ee.w);
        __stcs(&out[idx], o);
    }
}

extern "C" void kernel_launch(void* const* d_in, const int* in_sizes, int n_in,
                              void* d_out, int out_size) {
    const float4* images = (const float4*)d_in[0];
    const float4* e      = (const float4*)d_in[1];
    const int*    t      = (const int*)d_in[2];
    float4* out          = (float4*)d_out;

    const int B = in_sizes[2];
    const int total4 = B * 196;

    ddpm_mix_kernel<<<GRID, BLK>>>(images, e, t, out, total4);
}

// round 15
// speedup vs baseline: 1.0646x; 1.0646x over previous
#include <cuda_runtime.h>
#include <cuda_bf16.h>

#define T_STEPS 1000
#define BETA_1 1e-4
#define BETA_T 0.02

// ---- compile-time table: (sqrt(alpha_bar[t]), sqrt(1-alpha_bar[t])) ----
// Depends only on compile-time constants; baked into __constant__ memory so
// the graph has a single kernel node and zero table-init cost at runtime.

struct ScaleTable {
    float2 v[T_STEPS];
};

constexpr double csqrt(double x) {
    double g = x > 1.0 ? x : 1.0;
    for (int i = 0; i < 60; ++i) g = 0.5 * (g + x / g);
    return g;
}

constexpr ScaleTable make_table() {
    ScaleTable tbl{};
    const double slope = (BETA_T - BETA_1) / (double)(T_STEPS - 1);
    double ab = 1.0;
    for (int i = 0; i < T_STEPS; ++i) {
        double beta = BETA_1 + slope * (double)i;
        ab *= (1.0 - beta);
        tbl.v[i].x = (float)csqrt(ab);
        tbl.v[i].y = (float)csqrt(1.0 - ab);
    }
    return tbl;
}

__constant__ ScaleTable g_scales = make_table();

// ---- mix kernel: 1 float4 per thread, 3 linear DRAM streams, streaming hints ----
// FINAL CONFIG (best measured: R7). HBM-roofline-bound: 616 MB irreducible
// traffic @ ~6.86 TB/s achieved => ~89-90 us. Flat one-shot CTAs beat both
// larger per-thread tiling (occupancy loss) and persistent grid-stride
// (row-locality + scheduling loss). total4 = B * 196; divides 512 exactly.

#define BLK 512

__global__ void __launch_bounds__(BLK) ddpm_mix_kernel(
    const float4* __restrict__ images,
    const float4* __restrict__ e,
    const int* __restrict__ t,
    float4* __restrict__ out,
    int total4)
{
    const int idx = blockIdx.x * BLK + threadIdx.x;
    if (idx >= total4) return;

    // Front-batch both 16B loads (evict-first: data is touched exactly once)
    float4 im = __ldcs(&images[idx]);
    float4 ee = __ldcs(&e[idx]);

    const unsigned b = (unsigned)idx / 196u;       // magic-mul division
    const int ti = __ldg(&t[b]);                   // alpha_bar index = t (t_s-1)
    const float2 sc = g_scales.v[ti];

    float4 o;
    o.x = fmaf(sc.x, im.x, sc.y * ee.x);
    o.y = fmaf(sc.x, im.y, sc.y * ee.y);
    o.z = fmaf(sc.x, im.z, sc.y * ee.z);
    o.w = fmaf(sc.x, im.w, sc.y * ee.w);
    __stcs(&out[idx], o);
}

extern "C" void kernel_launch(void* const* d_in, const int* in_sizes, int n_in,
                              void* d_out, int out_size) {
    const float4* images = (const float4*)d_in[0];
    const float4* e      = (const float4*)d_in[1];
    const int*    t      = (const int*)d_in[2];
    float4* out          = (float4*)d_out;

    const int B = in_sizes[2];
    const int total4 = B * 196;
    const int grid = (total4 + BLK - 1) / BLK;

    ddpm_mix_kernel<<<grid, BLK>>>(images, e, t, out, total4);
}

// round 16
// speedup vs baseline: 1.0650x; 1.0004x over previous
#include <cuda_runtime.h>
#include <cuda_bf16.h>

#define T_STEPS 1000
#define BETA_1 1e-4
#define BETA_T 0.02

// ---- compile-time table: (sqrt(alpha_bar[t]), sqrt(1-alpha_bar[t])) ----
// Depends only on compile-time constants; baked into __constant__ memory so
// the graph has a single kernel node and zero table-init cost at runtime.
// Double-precision compile-time cumprod + Newton sqrt: more accurate than the
// reference's fp32 cumprod (measured rel_err 1.7e-7, threshold 1e-3).

struct ScaleTable {
    float2 v[T_STEPS];
};

constexpr double csqrt(double x) {
    double g = x > 1.0 ? x : 1.0;
    for (int i = 0; i < 60; ++i) g = 0.5 * (g + x / g);
    return g;
}

constexpr ScaleTable make_table() {
    ScaleTable tbl{};
    const double slope = (BETA_T - BETA_1) / (double)(T_STEPS - 1);
    double ab = 1.0;
    for (int i = 0; i < T_STEPS; ++i) {
        double beta = BETA_1 + slope * (double)i;
        ab *= (1.0 - beta);
        tbl.v[i].x = (float)csqrt(ab);
        tbl.v[i].y = (float)csqrt(1.0 - ab);
    }
    return tbl;
}

__constant__ ScaleTable g_scales = make_table();

// ---- mix kernel: 1 float4 per thread, 3 linear DRAM streams, streaming hints ----
// FINAL CONFIG. HBM-roofline-bound: 616 MB irreducible traffic @ ~6.8-6.9 TB/s
// achieved => ~90 us timed. Measured across the session:
//   - BLK=512 beats 256 and 1024; flat one-shot CTAs beat persistent
//     grid-stride (loop structure breaks load front-batching + row locality)
//     and beat 2x/4x per-thread tiling (register growth costs occupancy,
//     and chip-wide MLP = resident warps x per-warp MLP favors occupancy).
//   - .cs evict-first hints on all streams: data touched exactly once.
// total4 = B * 196 (784 floats per image = 196 float4); divides 512 exactly.

#define BLK 512

__global__ void __launch_bounds__(BLK) ddpm_mix_kernel(
    const float4* __restrict__ images,
    const float4* __restrict__ e,
    const int* __restrict__ t,
    float4* __restrict__ out,
    int total4)
{
    const int idx = blockIdx.x * BLK + threadIdx.x;
    if (idx >= total4) return;

    // Front-batch both 16B loads (evict-first: data is touched exactly once)
    float4 im = __ldcs(&images[idx]);
    float4 ee = __ldcs(&e[idx]);

    const unsigned b = (unsigned)idx / 196u;       // magic-mul division
    const int ti = __ldg(&t[b]);                   // alpha_bar index = t (t_s-1)
    const float2 sc = g_scales.v[ti];

    float4 o;
    o.x = fmaf(sc.x, im.x, sc.y * ee.x);
    o.y = fmaf(sc.x, im.y, sc.y * ee.y);
    o.z = fmaf(sc.x, im.z, sc.y * ee.z);
    o.w = fmaf(sc.x, im.w, sc.y * ee.w);
    __stcs(&out[idx], o);
}

extern "C" void kernel_launch(void* const* d_in, const int* in_sizes, int n_in,
                              void* d_out, int out_size) {
    const float4* images = (const float4*)d_in[0];
    const float4* e      = (const float4*)d_in[1];
    const int*    t      = (const int*)d_in[2];
    float4* out          = (float4*)d_out;

    const int B = in_sizes[2];
    const int total4 = B * 196;
    const int grid = (total4 + BLK - 1) / BLK;

    ddpm_mix_kernel<<<grid, BLK>>>(images, e, t, out, total4);
}